// round 7
// baseline (speedup 1.0000x reference)
#include <cuda_runtime.h>
#include <cstddef>

#define BATCH 2
#define NSINK 1024
#define NSRC  4096
#define DIM   512          // sink_dim == src_dim == hid
#define HID   512
#define NH    8
#define HD    64           // head dim
#define LNEPS 1e-6f
#define ATTEPS 1e-6f

// ---------------- static scratch (no allocations allowed) ----------------
__device__ float g_snorm[BATCH * NSINK * DIM];            // 4 MB
__device__ float g_cnorm[BATCH * NSRC  * DIM];            // 16 MB
__device__ float g_q    [BATCH * NSINK * HID];            // 4 MB
__device__ float g_kv   [BATCH * NSRC  * 2 * HID];        // 32 MB
__device__ float g_sim  [(size_t)BATCH * NH * NSINK * NSRC]; // 256 MB
__device__ float g_colm [BATCH * NH * NSRC];              // per-column max
__device__ float g_colz [BATCH * NH * NSRC];              // per-column 1/sum
__device__ float g_o    [BATCH * NSINK * HID];            // 4 MB

// ---------------- block reduction (deadlock-free) ----------------
// All lanes of warp 0 execute the cross-warp phase, so the full mask is valid.
template<int NT>
__device__ __forceinline__ float block_sum(float v) {
    __shared__ float sh[32];
    #pragma unroll
    for (int o = 16; o; o >>= 1) v += __shfl_xor_sync(0xffffffffu, v, o);
    if ((threadIdx.x & 31) == 0) sh[threadIdx.x >> 5] = v;
    __syncthreads();
    if (threadIdx.x < 32) {                       // entire warp 0 active
        float x = (threadIdx.x < NT / 32) ? sh[threadIdx.x] : 0.f;
        #pragma unroll
        for (int o = 16; o; o >>= 1) x += __shfl_xor_sync(0xffffffffu, x, o);
        if (threadIdx.x == 0) sh[0] = x;
    }
    __syncthreads();
    v = sh[0];
    __syncthreads();
    return v;
}

// ---------------- LayerNorm: one block per row of 512 ----------------
__global__ __launch_bounds__(128) void ln_kernel(
    const float* __restrict__ x, const float* __restrict__ gamma,
    const float* __restrict__ beta, float* __restrict__ y)
{
    const float* xr = x + (size_t)blockIdx.x * DIM;
    float* yr = y + (size_t)blockIdx.x * DIM;
    float v[4];
    float s = 0.f;
    #pragma unroll
    for (int i = 0; i < 4; i++) { v[i] = xr[threadIdx.x + 128 * i]; s += v[i]; }
    float mu = block_sum<128>(s) * (1.f / DIM);
    float var = 0.f;
    #pragma unroll
    for (int i = 0; i < 4; i++) { float d = v[i] - mu; var += d * d; }
    var = block_sum<128>(var) * (1.f / DIM);
    float r = rsqrtf(var + LNEPS);
    #pragma unroll
    for (int i = 0; i < 4; i++) {
        int c = threadIdx.x + 128 * i;
        yr[c] = (v[i] - mu) * r * gamma[c] + beta[c];
    }
}

// ======== 128x128-tile fp32 GEMM + bias: C[M,N]=A[M,K]@B[K,N]+bias ========
// 256 threads, 8x8 per thread (rows ty*4 + {0,64}, cols tx*4 + {0,64}).
// Requires M%128==0, N%128==0, K%16==0.
__global__ __launch_bounds__(256) void gemm128(
    const float* __restrict__ A, const float* __restrict__ B,
    const float* __restrict__ bias, float* __restrict__ C,
    int M, int N, int K)
{
    __shared__ float As[16][136];   // transposed: As[k][row]
    __shared__ float Bs[16][136];   // Bs[k][col]
    const int t  = threadIdx.x;
    const int tx = t & 15, ty = t >> 4;
    const int i0 = blockIdx.y * 128, j0 = blockIdx.x * 128;
    const int ar = t >> 2,  ac4 = (t & 3) << 2;     // A loader
    const int br = t >> 5,  bc4 = (t & 31) << 2;    // B loader
    float acc[8][8] = {};
    for (int kt = 0; kt < K; kt += 16) {
        float4 a0 = *(const float4*)&A[(size_t)(i0 + ar) * K + kt + ac4];
        float4 a1 = *(const float4*)&A[(size_t)(i0 + ar + 64) * K + kt + ac4];
        As[ac4 + 0][ar] = a0.x; As[ac4 + 1][ar] = a0.y;
        As[ac4 + 2][ar] = a0.z; As[ac4 + 3][ar] = a0.w;
        As[ac4 + 0][ar + 64] = a1.x; As[ac4 + 1][ar + 64] = a1.y;
        As[ac4 + 2][ar + 64] = a1.z; As[ac4 + 3][ar + 64] = a1.w;
        *(float4*)&Bs[br][bc4]     = *(const float4*)&B[(size_t)(kt + br) * N + j0 + bc4];
        *(float4*)&Bs[br + 8][bc4] = *(const float4*)&B[(size_t)(kt + br + 8) * N + j0 + bc4];
        __syncthreads();
        #pragma unroll
        for (int kk = 0; kk < 16; kk++) {
            float4 av0 = *(const float4*)&As[kk][ty * 4];
            float4 av1 = *(const float4*)&As[kk][ty * 4 + 64];
            float4 bv0 = *(const float4*)&Bs[kk][tx * 4];
            float4 bv1 = *(const float4*)&Bs[kk][tx * 4 + 64];
            float a[8] = {av0.x, av0.y, av0.z, av0.w, av1.x, av1.y, av1.z, av1.w};
            float b[8] = {bv0.x, bv0.y, bv0.z, bv0.w, bv1.x, bv1.y, bv1.z, bv1.w};
            #pragma unroll
            for (int r = 0; r < 8; r++)
                #pragma unroll
                for (int c = 0; c < 8; c++) acc[r][c] += a[r] * b[c];
        }
        __syncthreads();
    }
    #pragma unroll
    for (int cs = 0; cs < 2; cs++) {
        int jc = j0 + cs * 64 + tx * 4;
        float4 bi = *(const float4*)&bias[jc];
        #pragma unroll
        for (int rs = 0; rs < 2; rs++)
            #pragma unroll
            for (int r = 0; r < 4; r++) {
                int row = i0 + rs * 64 + ty * 4 + r;
                float4 v;
                v.x = acc[rs * 4 + r][cs * 4 + 0] + bi.x;
                v.y = acc[rs * 4 + r][cs * 4 + 1] + bi.y;
                v.z = acc[rs * 4 + r][cs * 4 + 2] + bi.z;
                v.w = acc[rs * 4 + r][cs * 4 + 3] + bi.w;
                *(float4*)&C[(size_t)row * N + jc] = v;
            }
    }
}

// ======== sim = scale * Q Kᵀ per (b,h): 128x128 tile, K=64 ========
__global__ __launch_bounds__(256) void sim128(
    const float* __restrict__ q, const float* __restrict__ kv,
    float* __restrict__ sim, float scale)
{
    __shared__ float As[16][136];
    __shared__ float Bs[16][136];
    const int bh = blockIdx.z, b = bh / NH, h = bh % NH;
    const int ldb = 2 * HID;
    const float* A  = q  + (size_t)b * NSINK * HID + h * HD;          // lda = HID
    const float* Bk = kv + (size_t)b * NSRC * ldb + h * HD;
    float* C = sim + (size_t)bh * NSINK * NSRC;
    const int t  = threadIdx.x;
    const int tx = t & 15, ty = t >> 4;
    const int i0 = blockIdx.y * 128, j0 = blockIdx.x * 128;
    const int ar = t >> 2, ac4 = (t & 3) << 2;   // shared loader coords (both A & B)
    float acc[8][8] = {};
    for (int kt = 0; kt < HD; kt += 16) {
        float4 a0 = *(const float4*)&A[(size_t)(i0 + ar) * HID + kt + ac4];
        float4 a1 = *(const float4*)&A[(size_t)(i0 + ar + 64) * HID + kt + ac4];
        As[ac4 + 0][ar] = a0.x; As[ac4 + 1][ar] = a0.y;
        As[ac4 + 2][ar] = a0.z; As[ac4 + 3][ar] = a0.w;
        As[ac4 + 0][ar + 64] = a1.x; As[ac4 + 1][ar + 64] = a1.y;
        As[ac4 + 2][ar + 64] = a1.z; As[ac4 + 3][ar + 64] = a1.w;
        float4 b0 = *(const float4*)&Bk[(size_t)(j0 + ar) * ldb + kt + ac4];
        float4 b1 = *(const float4*)&Bk[(size_t)(j0 + ar + 64) * ldb + kt + ac4];
        Bs[ac4 + 0][ar] = b0.x; Bs[ac4 + 1][ar] = b0.y;
        Bs[ac4 + 2][ar] = b0.z; Bs[ac4 + 3][ar] = b0.w;
        Bs[ac4 + 0][ar + 64] = b1.x; Bs[ac4 + 1][ar + 64] = b1.y;
        Bs[ac4 + 2][ar + 64] = b1.z; Bs[ac4 + 3][ar + 64] = b1.w;
        __syncthreads();
        #pragma unroll
        for (int kk = 0; kk < 16; kk++) {
            float4 av0 = *(const float4*)&As[kk][ty * 4];
            float4 av1 = *(const float4*)&As[kk][ty * 4 + 64];
            float4 bv0 = *(const float4*)&Bs[kk][tx * 4];
            float4 bv1 = *(const float4*)&Bs[kk][tx * 4 + 64];
            float a[8] = {av0.x, av0.y, av0.z, av0.w, av1.x, av1.y, av1.z, av1.w};
            float bb[8] = {bv0.x, bv0.y, bv0.z, bv0.w, bv1.x, bv1.y, bv1.z, bv1.w};
            #pragma unroll
            for (int r = 0; r < 8; r++)
                #pragma unroll
                for (int c = 0; c < 8; c++) acc[r][c] += a[r] * bb[c];
        }
        __syncthreads();
    }
    #pragma unroll
    for (int cs = 0; cs < 2; cs++)
        #pragma unroll
        for (int rs = 0; rs < 2; rs++)
            #pragma unroll
            for (int r = 0; r < 4; r++) {
                int row = i0 + rs * 64 + ty * 4 + r;
                int jc  = j0 + cs * 64 + tx * 4;
                float4 v;
                v.x = acc[rs * 4 + r][cs * 4 + 0] * scale;
                v.y = acc[rs * 4 + r][cs * 4 + 1] * scale;
                v.z = acc[rs * 4 + r][cs * 4 + 2] * scale;
                v.w = acc[rs * 4 + r][cs * 4 + 3] * scale;
                *(float4*)&C[(size_t)row * NSRC + jc] = v;
            }
}

// ======== per-column softmax stats: m_j and 1/z_j (over i axis) ========
__global__ __launch_bounds__(256) void colstat_kernel(
    const float* __restrict__ sim, float* __restrict__ colm, float* __restrict__ colz)
{
    const int bh = blockIdx.y;
    const int j = blockIdx.x * 256 + threadIdx.x;
    const float* S = sim + (size_t)bh * NSINK * NSRC;
    float m = -1e30f, z = 0.f;
    for (int i = 0; i < NSINK; i++) {
        float x = S[(size_t)i * NSRC + j];
        float mn = fmaxf(m, x);               // branch-free online update
        z = z * __expf(m - mn) + __expf(x - mn);
        m = mn;
    }
    colm[bh * NSRC + j] = m;
    colz[bh * NSRC + j] = 1.f / z;
}

// ======== out = (attn @ V) / rowsum; attn materialized on the fly ========
// 128x64 tile per block; 256 threads, 8 rows x 4 cols per thread.
__global__ __launch_bounds__(256) void av128(
    const float* __restrict__ sim, const float* __restrict__ kv,
    const float* __restrict__ colm, const float* __restrict__ colz,
    float* __restrict__ o)
{
    __shared__ float As[16][136];   // As[k][row] = attn value
    __shared__ float Bs[16][72];    // Bs[k][col] = V
    const int bh = blockIdx.z, b = bh / NH, h = bh % NH;
    const int ldv = 2 * HID;
    const float* A = sim + (size_t)bh * NSINK * NSRC;
    const float* V = kv + (size_t)b * NSRC * ldv + HID + h * HD;
    const float* cm = colm + bh * NSRC;
    const float* cz = colz + bh * NSRC;
    const int t  = threadIdx.x;
    const int tx = t & 15, ty = t >> 4;
    const int i0 = blockIdx.y * 128;
    const int ar = t >> 2, ac4 = (t & 3) << 2;   // A loader
    const int vr = t >> 4, vc4 = (t & 15) << 2;  // V loader
    float acc[8][4] = {};
    float rsum[8]   = {};
    for (int kt = 0; kt < NSRC; kt += 16) {
        float4 m4 = *(const float4*)&cm[kt + ac4];
        float4 z4 = *(const float4*)&cz[kt + ac4];
        float4 s0 = *(const float4*)&A[(size_t)(i0 + ar) * NSRC + kt + ac4];
        float4 s1 = *(const float4*)&A[(size_t)(i0 + ar + 64) * NSRC + kt + ac4];
        As[ac4 + 0][ar] = __expf(s0.x - m4.x) * z4.x + ATTEPS;
        As[ac4 + 1][ar] = __expf(s0.y - m4.y) * z4.y + ATTEPS;
        As[ac4 + 2][ar] = __expf(s0.z - m4.z) * z4.z + ATTEPS;
        As[ac4 + 3][ar] = __expf(s0.w - m4.w) * z4.w + ATTEPS;
        As[ac4 + 0][ar + 64] = __expf(s1.x - m4.x) * z4.x + ATTEPS;
        As[ac4 + 1][ar + 64] = __expf(s1.y - m4.y) * z4.y + ATTEPS;
        As[ac4 + 2][ar + 64] = __expf(s1.z - m4.z) * z4.z + ATTEPS;
        As[ac4 + 3][ar + 64] = __expf(s1.w - m4.w) * z4.w + ATTEPS;
        *(float4*)&Bs[vr][vc4] = *(const float4*)&V[(size_t)(kt + vr) * ldv + vc4];
        __syncthreads();
        #pragma unroll
        for (int kk = 0; kk < 16; kk++) {
            float4 av0 = *(const float4*)&As[kk][ty * 4];
            float4 av1 = *(const float4*)&As[kk][ty * 4 + 64];
            float4 bv  = *(const float4*)&Bs[kk][tx * 4];
            float a[8] = {av0.x, av0.y, av0.z, av0.w, av1.x, av1.y, av1.z, av1.w};
            float bb[4] = {bv.x, bv.y, bv.z, bv.w};
            #pragma unroll
            for (int r = 0; r < 8; r++) {
                rsum[r] += a[r];
                #pragma unroll
                for (int c = 0; c < 4; c++) acc[r][c] += a[r] * bb[c];
            }
        }
        __syncthreads();
    }
    #pragma unroll
    for (int rs = 0; rs < 2; rs++)
        #pragma unroll
        for (int r = 0; r < 4; r++) {
            int i = i0 + rs * 64 + ty * 4 + r;
            float inv = 1.f / rsum[rs * 4 + r];
            float4 v;
            v.x = acc[rs * 4 + r][0] * inv;
            v.y = acc[rs * 4 + r][1] * inv;
            v.z = acc[rs * 4 + r][2] * inv;
            v.w = acc[rs * 4 + r][3] * inv;
            *(float4*)&o[(size_t)b * NSINK * HID + (size_t)i * HID + h * HD + tx * 4] = v;
        }
}

// ---------------- launch ----------------
extern "C" void kernel_launch(void* const* d_in, const int* in_sizes, int n_in,
                              void* d_out, int out_size)
{
    const float* sink    = (const float*)d_in[0];
    const float* source  = (const float*)d_in[1];
    const float* gamma_s = (const float*)d_in[2];
    const float* beta_s  = (const float*)d_in[3];
    const float* gamma_c = (const float*)d_in[4];
    const float* beta_c  = (const float*)d_in[5];
    const float* Wq      = (const float*)d_in[6];
    const float* bq      = (const float*)d_in[7];
    const float* Wkv     = (const float*)d_in[8];
    const float* bkv     = (const float*)d_in[9];
    const float* Wo      = (const float*)d_in[10];
    const float* bo      = (const float*)d_in[11];
    float* out = (float*)d_out;

    float *snorm, *cnorm, *q, *kv, *sim, *colm, *colz, *o;
    cudaGetSymbolAddress((void**)&snorm, g_snorm);
    cudaGetSymbolAddress((void**)&cnorm, g_cnorm);
    cudaGetSymbolAddress((void**)&q,     g_q);
    cudaGetSymbolAddress((void**)&kv,    g_kv);
    cudaGetSymbolAddress((void**)&sim,   g_sim);
    cudaGetSymbolAddress((void**)&colm,  g_colm);
    cudaGetSymbolAddress((void**)&colz,  g_colz);
    cudaGetSymbolAddress((void**)&o,     g_o);

    // 1. pre-norms
    ln_kernel<<<BATCH * NSINK, 128>>>(sink, gamma_s, beta_s, snorm);
    ln_kernel<<<BATCH * NSRC, 128>>>(source, gamma_c, beta_c, cnorm);

    // 2. projections
    gemm128<<<dim3(HID / 128, BATCH * NSINK / 128), 256>>>(
        snorm, Wq, bq, q, BATCH * NSINK, HID, DIM);
    gemm128<<<dim3(2 * HID / 128, BATCH * NSRC / 128), 256>>>(
        cnorm, Wkv, bkv, kv, BATCH * NSRC, 2 * HID, DIM);

    // 3. sim = scale * Q Kᵀ
    sim128<<<dim3(NSRC / 128, NSINK / 128, BATCH * NH), 256>>>(q, kv, sim, 0.125f);

    // 4. per-column softmax stats
    colstat_kernel<<<dim3(NSRC / 256, BATCH * NH), 256>>>(sim, colm, colz);

    // 5. AV with on-the-fly attn + fused row renorm
    av128<<<dim3(1, NSINK / 128, BATCH * NH), 256>>>(sim, kv, colm, colz, o);

    // 6. output projection
    gemm128<<<dim3(DIM / 128, BATCH * NSINK / 128), 256>>>(
        o, Wo, bo, out, BATCH * NSINK, DIM, DIM);
}

// round 10
// speedup vs baseline: 1.3176x; 1.3176x over previous
#include <cuda_runtime.h>
#include <cuda_fp16.h>
#include <mma.h>
#include <cstddef>

using namespace nvcuda;

#define BATCH 2
#define NSINK 1024
#define NSRC  4096
#define DIM   512          // sink_dim == src_dim == hid
#define HID   512
#define NH    8
#define HD    64           // head dim
#define LNEPS 1e-6f
#define ATTEPS 1e-6f

// ---------------- static scratch (no allocations allowed) ----------------
__device__ __half g_snorm_h[BATCH * NSINK * DIM];
__device__ __half g_cnorm_h[BATCH * NSRC  * DIM];
__device__ __half g_q_h   [BATCH * NSINK * HID];
__device__ __half g_kv_h  [BATCH * NSRC  * 2 * HID];
__device__ __half g_sim_h [(size_t)BATCH * NH * NSINK * NSRC];   // 128 MB
__device__ float  g_colm  [BATCH * NH * NSRC];
__device__ float  g_colz  [BATCH * NH * NSRC];
__device__ __half g_o_h   [BATCH * NSINK * HID];
__device__ __half g_wq_h  [DIM * HID];
__device__ __half g_wkv_h [DIM * 2 * HID];
__device__ __half g_wo_h  [HID * DIM];

// ---------------- fp32 -> fp16 convert ----------------
__global__ void cvt_f2h(const float* __restrict__ s, __half* __restrict__ d, int n) {
    int i = blockIdx.x * 256 + threadIdx.x;
    if (i < n) d[i] = __float2half(s[i]);
}

// ---------------- block reduction (deadlock-free) ----------------
template<int NT>
__device__ __forceinline__ float block_sum(float v) {
    __shared__ float sh[32];
    #pragma unroll
    for (int o = 16; o; o >>= 1) v += __shfl_xor_sync(0xffffffffu, v, o);
    if ((threadIdx.x & 31) == 0) sh[threadIdx.x >> 5] = v;
    __syncthreads();
    if (threadIdx.x < 32) {
        float x = (threadIdx.x < NT / 32) ? sh[threadIdx.x] : 0.f;
        #pragma unroll
        for (int o = 16; o; o >>= 1) x += __shfl_xor_sync(0xffffffffu, x, o);
        if (threadIdx.x == 0) sh[0] = x;
    }
    __syncthreads();
    v = sh[0];
    __syncthreads();
    return v;
}

// ---------------- LayerNorm -> fp16 output ----------------
__global__ __launch_bounds__(128) void ln_kernel(
    const float* __restrict__ x, const float* __restrict__ gamma,
    const float* __restrict__ beta, __half* __restrict__ y)
{
    const float* xr = x + (size_t)blockIdx.x * DIM;
    __half* yr = y + (size_t)blockIdx.x * DIM;
    float v[4];
    float s = 0.f;
    #pragma unroll
    for (int i = 0; i < 4; i++) { v[i] = xr[threadIdx.x + 128 * i]; s += v[i]; }
    float mu = block_sum<128>(s) * (1.f / DIM);
    float var = 0.f;
    #pragma unroll
    for (int i = 0; i < 4; i++) { float d = v[i] - mu; var += d * d; }
    var = block_sum<128>(var) * (1.f / DIM);
    float r = rsqrtf(var + LNEPS);
    #pragma unroll
    for (int i = 0; i < 4; i++) {
        int c = threadIdx.x + 128 * i;
        yr[c] = __float2half((v[i] - mu) * r * gamma[c] + beta[c]);
    }
}

// ======== wmma GEMM + bias: C[M,N] = A_h[M,K] @ B_h[K,N] + bias ========
// 128x128 block tile, 8 warps (32x64 each), k-step 32. M,N%128==0, K%32==0.
template<bool OUT_HALF>
__global__ __launch_bounds__(256) void gemm_wmma(
    const __half* __restrict__ A, const __half* __restrict__ B,
    const float* __restrict__ bias, void* __restrict__ Cv,
    int M, int N, int K)
{
    __shared__ __half As[128 * 40];    // [row][k] ld 40
    __shared__ __half Bs[32 * 136];    // [k][col] ld 136
    __shared__ float  stage[8][16 * 20];
    const int t = threadIdx.x, w = t >> 5, lane = t & 31;
    const int wr = w >> 1, wc = w & 1;
    const int i0 = blockIdx.y * 128, j0 = blockIdx.x * 128;
    wmma::fragment<wmma::accumulator, 16, 16, 16, float> acc[2][4];
    #pragma unroll
    for (int m = 0; m < 2; m++)
        #pragma unroll
        for (int n = 0; n < 4; n++) wmma::fill_fragment(acc[m][n], 0.f);

    for (int kt = 0; kt < K; kt += 32) {
        #pragma unroll
        for (int c = t; c < 512; c += 256) {           // A: 128x32
            int r = c >> 2, cc = (c & 3) << 3;
            *(uint4*)&As[r * 40 + cc] = *(const uint4*)&A[(size_t)(i0 + r) * K + kt + cc];
        }
        #pragma unroll
        for (int c = t; c < 512; c += 256) {           // B: 32x128
            int r = c >> 4, cc = (c & 15) << 3;
            *(uint4*)&Bs[r * 136 + cc] = *(const uint4*)&B[(size_t)(kt + r) * N + j0 + cc];
        }
        __syncthreads();
        #pragma unroll
        for (int kk = 0; kk < 2; kk++) {
            wmma::fragment<wmma::matrix_a, 16, 16, 16, __half, wmma::row_major> af[2];
            wmma::fragment<wmma::matrix_b, 16, 16, 16, __half, wmma::row_major> bf[4];
            #pragma unroll
            for (int m = 0; m < 2; m++)
                wmma::load_matrix_sync(af[m], &As[(wr * 32 + m * 16) * 40 + kk * 16], 40);
            #pragma unroll
            for (int n = 0; n < 4; n++)
                wmma::load_matrix_sync(bf[n], &Bs[(kk * 16) * 136 + wc * 64 + n * 16], 136);
            #pragma unroll
            for (int m = 0; m < 2; m++)
                #pragma unroll
                for (int n = 0; n < 4; n++)
                    wmma::mma_sync(acc[m][n], af[m], bf[n], acc[m][n]);
        }
        __syncthreads();
    }
    // epilogue: stage each 16x16 frag, add bias, write
    #pragma unroll
    for (int m = 0; m < 2; m++)
        #pragma unroll
        for (int n = 0; n < 4; n++) {
            wmma::store_matrix_sync(stage[w], acc[m][n], 20, wmma::mem_row_major);
            __syncwarp();
            int row = lane >> 1, c0 = (lane & 1) << 3;
            int gi = i0 + wr * 32 + m * 16 + row;
            int gj = j0 + wc * 64 + n * 16 + c0;
            #pragma unroll
            for (int c = 0; c < 8; c++) {
                float vv = stage[w][row * 20 + c0 + c] + bias[gj + c];
                if (OUT_HALF) ((__half*)Cv)[(size_t)gi * N + gj + c] = __float2half(vv);
                else          ((float*)Cv)[(size_t)gi * N + gj + c] = vv;
            }
            __syncwarp();
        }
}

// ======== sim = scale * q kᵀ per (b,h), fp16 out ========
__global__ __launch_bounds__(256) void sim_wmma(
    const __half* __restrict__ q, const __half* __restrict__ kv,
    __half* __restrict__ sim)
{
    __shared__ __half As[128 * 72];    // q  [i][d]  ld 72
    __shared__ __half Bs[128 * 72];    // k  [j][d]  ld 72
    __shared__ float  stage[8][16 * 20];
    const int bh = blockIdx.z, b = bh / NH, h = bh % NH;
    const __half* A  = q  + (size_t)b * NSINK * HID + h * HD;
    const __half* Bk = kv + (size_t)b * NSRC * (2 * HID) + h * HD;
    __half* C = sim + (size_t)bh * NSINK * NSRC;
    const int t = threadIdx.x, w = t >> 5, lane = t & 31;
    const int wr = w >> 1, wc = w & 1;
    const int i0 = blockIdx.y * 128, j0 = blockIdx.x * 128;

    #pragma unroll
    for (int c = t; c < 1024; c += 256) {              // 128x64 each
        int r = c >> 3, cc = (c & 7) << 3;
        *(uint4*)&As[r * 72 + cc] = *(const uint4*)&A[(size_t)(i0 + r) * HID + cc];
    }
    #pragma unroll
    for (int c = t; c < 1024; c += 256) {
        int r = c >> 3, cc = (c & 7) << 3;
        *(uint4*)&Bs[r * 72 + cc] = *(const uint4*)&Bk[(size_t)(j0 + r) * (2 * HID) + cc];
    }
    __syncthreads();

    wmma::fragment<wmma::accumulator, 16, 16, 16, float> acc[2][4];
    #pragma unroll
    for (int m = 0; m < 2; m++)
        #pragma unroll
        for (int n = 0; n < 4; n++) wmma::fill_fragment(acc[m][n], 0.f);
    #pragma unroll
    for (int kk = 0; kk < 4; kk++) {
        wmma::fragment<wmma::matrix_a, 16, 16, 16, __half, wmma::row_major> af[2];
        wmma::fragment<wmma::matrix_b, 16, 16, 16, __half, wmma::col_major> bf[4];
        #pragma unroll
        for (int m = 0; m < 2; m++)
            wmma::load_matrix_sync(af[m], &As[(wr * 32 + m * 16) * 72 + kk * 16], 72);
        #pragma unroll
        for (int n = 0; n < 4; n++)
            wmma::load_matrix_sync(bf[n], &Bs[(wc * 64 + n * 16) * 72 + kk * 16], 72);
        #pragma unroll
        for (int m = 0; m < 2; m++)
            #pragma unroll
            for (int n = 0; n < 4; n++)
                wmma::mma_sync(acc[m][n], af[m], bf[n], acc[m][n]);
    }
    #pragma unroll
    for (int m = 0; m < 2; m++)
        #pragma unroll
        for (int n = 0; n < 4; n++) {
            wmma::store_matrix_sync(stage[w], acc[m][n], 20, wmma::mem_row_major);
            __syncwarp();
            int row = lane >> 1, c0 = (lane & 1) << 3;
            int gi = i0 + wr * 32 + m * 16 + row;
            int gj = j0 + wc * 64 + n * 16 + c0;
            #pragma unroll
            for (int c = 0; c < 8; c++)
                C[(size_t)gi * NSRC + gj + c] =
                    __float2half(stage[w][row * 20 + c0 + c] * 0.125f);
            __syncwarp();
        }
}

// ======== per-column softmax stats over i (half2-vectorized) ========
__global__ __launch_bounds__(256) void colstat_h(
    const __half* __restrict__ sim, float* __restrict__ colm, float* __restrict__ colz)
{
    const int bh = blockIdx.y;
    const int j = blockIdx.x * 512 + threadIdx.x * 2;
    const __half* S = sim + (size_t)bh * NSINK * NSRC;
    float mx = -1e30f, my = -1e30f, zx = 0.f, zy = 0.f;
    for (int i = 0; i < NSINK; i++) {
        float2 x = __half22float2(*(const __half2*)&S[(size_t)i * NSRC + j]);
        float mnx = fmaxf(mx, x.x);
        zx = zx * __expf(mx - mnx) + __expf(x.x - mnx);
        mx = mnx;
        float mny = fmaxf(my, x.y);
        zy = zy * __expf(my - mny) + __expf(x.y - mny);
        my = mny;
    }
    colm[bh * NSRC + j]     = mx;
    colm[bh * NSRC + j + 1] = my;
    colz[bh * NSRC + j]     = 1.f / zx;
    colz[bh * NSRC + j + 1] = 1.f / zy;
}

// ======== out = (attn @ V_ext) / rowsum; attn built on the fly ========
// V extended with a ones column at n=64 so acc col 64 = exact row sum.
__global__ __launch_bounds__(256) void av_wmma(
    const __half* __restrict__ sim, const __half* __restrict__ kv,
    const float* __restrict__ colm, const float* __restrict__ colz,
    __half* __restrict__ o)
{
    __shared__ __half As[128 * 72];    // attn [i][j64] ld 72
    __shared__ __half Bs[64 * 88];     // V_ext [j][88] ld 88
    __shared__ float  stage[8][16 * 20];
    __shared__ float  rs[8][16];
    const int bh = blockIdx.z, b = bh / NH, h = bh % NH;
    const __half* A = sim + (size_t)bh * NSINK * NSRC;
    const __half* V = kv + (size_t)b * NSRC * (2 * HID) + HID + h * HD;
    const float* cm = colm + bh * NSRC;
    const float* cz = colz + bh * NSRC;
    const int t = threadIdx.x, w = t >> 5, lane = t & 31;
    const int i0 = blockIdx.y * 128;

    wmma::fragment<wmma::accumulator, 16, 16, 16, float> acc[5];
    #pragma unroll
    for (int n = 0; n < 5; n++) wmma::fill_fragment(acc[n], 0.f);

    for (int kt = 0; kt < NSRC; kt += 64) {
        // attn tile 128x64 (4096 half2)
        for (int e = t; e < 4096; e += 256) {
            int r = e >> 5, c2 = e & 31;
            int j = kt + c2 * 2;
            float2 sf = __half22float2(*(const __half2*)&A[(size_t)(i0 + r) * NSRC + j]);
            float2 mf = *(const float2*)&cm[j];
            float2 zf = *(const float2*)&cz[j];
            float a0 = __expf(sf.x - mf.x) * zf.x + ATTEPS;
            float a1 = __expf(sf.y - mf.y) * zf.y + ATTEPS;
            *(__half2*)&As[r * 72 + c2 * 2] = __floats2half2_rn(a0, a1);
        }
        // V tile 64x64
        #pragma unroll
        for (int c = t; c < 512; c += 256) {
            int r = c >> 3, cc = (c & 7) << 3;
            *(uint4*)&Bs[r * 88 + cc] = *(const uint4*)&V[(size_t)(kt + r) * (2 * HID) + cc];
        }
        // extension cols 64..87: ones column + zero pad
        for (int e = t; e < 64 * 24; e += 256) {
            int r = e / 24, cc = 64 + e % 24;
            Bs[r * 88 + cc] = __float2half(cc == 64 ? 1.f : 0.f);
        }
        __syncthreads();
        #pragma unroll
        for (int kk = 0; kk < 4; kk++) {
            wmma::fragment<wmma::matrix_a, 16, 16, 16, __half, wmma::row_major> af;
            wmma::load_matrix_sync(af, &As[(w * 16) * 72 + kk * 16], 72);
            #pragma unroll
            for (int n = 0; n < 5; n++) {
                wmma::fragment<wmma::matrix_b, 16, 16, 16, __half, wmma::row_major> bf;
                wmma::load_matrix_sync(bf, &Bs[(kk * 16) * 88 + n * 16], 88);
                wmma::mma_sync(acc[n], af, bf, acc[n]);
            }
        }
        __syncthreads();
    }
    // row sums from ones-column frag (col 64 = local col 0 of frag 4)
    wmma::store_matrix_sync(stage[w], acc[4], 20, wmma::mem_row_major);
    __syncwarp();
    if (lane < 16) rs[w][lane] = 1.f / stage[w][lane * 20 + 0];
    __syncwarp();
    #pragma unroll
    for (int n = 0; n < 4; n++) {
        wmma::store_matrix_sync(stage[w], acc[n], 20, wmma::mem_row_major);
        __syncwarp();
        int row = lane >> 1, c0 = (lane & 1) << 3;
        int gi = i0 + w * 16 + row;
        #pragma unroll
        for (int c = 0; c < 8; c++)
            o[(size_t)(b * NSINK + gi) * HID + h * HD + n * 16 + c0 + c] =
                __float2half(stage[w][row * 20 + c0 + c] * rs[w][row]);
        __syncwarp();
    }
}

// ---------------- launch ----------------
extern "C" void kernel_launch(void* const* d_in, const int* in_sizes, int n_in,
                              void* d_out, int out_size)
{
    const float* sink    = (const float*)d_in[0];
    const float* source  = (const float*)d_in[1];
    const float* gamma_s = (const float*)d_in[2];
    const float* beta_s  = (const float*)d_in[3];
    const float* gamma_c = (const float*)d_in[4];
    const float* beta_c  = (const float*)d_in[5];
    const float* Wq      = (const float*)d_in[6];
    const float* bq      = (const float*)d_in[7];
    const float* Wkv     = (const float*)d_in[8];
    const float* bkv     = (const float*)d_in[9];
    const float* Wo      = (const float*)d_in[10];
    const float* bo      = (const float*)d_in[11];
    float* out = (float*)d_out;

    __half *snorm_h, *cnorm_h, *q_h, *kv_h, *sim_h, *o_h, *wq_h, *wkv_h, *wo_h;
    float *colm, *colz;
    cudaGetSymbolAddress((void**)&snorm_h, g_snorm_h);
    cudaGetSymbolAddress((void**)&cnorm_h, g_cnorm_h);
    cudaGetSymbolAddress((void**)&q_h,     g_q_h);
    cudaGetSymbolAddress((void**)&kv_h,    g_kv_h);
    cudaGetSymbolAddress((void**)&sim_h,   g_sim_h);
    cudaGetSymbolAddress((void**)&colm,    g_colm);
    cudaGetSymbolAddress((void**)&colz,    g_colz);
    cudaGetSymbolAddress((void**)&o_h,     g_o_h);
    cudaGetSymbolAddress((void**)&wq_h,    g_wq_h);
    cudaGetSymbolAddress((void**)&wkv_h,   g_wkv_h);
    cudaGetSymbolAddress((void**)&wo_h,    g_wo_h);

    // 0. weight conversion
    cvt_f2h<<<(DIM * HID + 255) / 256, 256>>>(Wq, wq_h, DIM * HID);
    cvt_f2h<<<(DIM * 2 * HID + 255) / 256, 256>>>(Wkv, wkv_h, DIM * 2 * HID);
    cvt_f2h<<<(HID * DIM + 255) / 256, 256>>>(Wo, wo_h, HID * DIM);

    // 1. pre-norms (fp16 out)
    ln_kernel<<<BATCH * NSINK, 128>>>(sink, gamma_s, beta_s, snorm_h);
    ln_kernel<<<BATCH * NSRC, 128>>>(source, gamma_c, beta_c, cnorm_h);

    // 2. projections (tensor cores)
    gemm_wmma<true><<<dim3(HID / 128, BATCH * NSINK / 128), 256>>>(
        snorm_h, wq_h, bq, q_h, BATCH * NSINK, HID, DIM);
    gemm_wmma<true><<<dim3(2 * HID / 128, BATCH * NSRC / 128), 256>>>(
        cnorm_h, wkv_h, bkv, kv_h, BATCH * NSRC, 2 * HID, DIM);

    // 3. sim = scale * q kᵀ (fp16 out)
    sim_wmma<<<dim3(NSRC / 128, NSINK / 128, BATCH * NH), 256>>>(q_h, kv_h, sim_h);

    // 4. per-column softmax stats
    colstat_h<<<dim3(NSRC / 512, BATCH * NH), 256>>>(sim_h, colm, colz);

    // 5. AV with fused renorm (ones-column trick)
    av_wmma<<<dim3(1, NSINK / 128, BATCH * NH), 256>>>(sim_h, kv_h, colm, colz, o_h);

    // 6. output projection (fp32 out)
    gemm_wmma<false><<<dim3(DIM / 128, BATCH * NSINK / 128), 256>>>(
        o_h, wo_h, bo, out, BATCH * NSINK, DIM, DIM);
}

// round 12
// speedup vs baseline: 1.5609x; 1.1846x over previous
#include <cuda_runtime.h>
#include <cuda_fp16.h>
#include <mma.h>
#include <cstddef>

using namespace nvcuda;

#define BATCH 2
#define NSINK 1024
#define NSRC  4096
#define DIM   512          // sink_dim == src_dim == hid
#define HID   512
#define NH    8
#define HD    64           // head dim
#define LNEPS 1e-6f
#define ATTEPS 1e-6f

// ---------------- static scratch (no allocations allowed) ----------------
__device__ __half g_snorm_h[BATCH * NSINK * DIM];
__device__ __half g_cnorm_h[BATCH * NSRC  * DIM];
__device__ __half g_q_h   [BATCH * NSINK * HID];
__device__ __half g_kv_h  [BATCH * NSRC  * 2 * HID];
__device__ __half g_p_h   [(size_t)BATCH * NH * NSINK * NSRC];   // exp(sim), 128 MB
__device__ float  g_colz  [BATCH * NH * NSRC];                   // 1 / colsum
__device__ __half g_o_h   [BATCH * NSINK * HID];
__device__ __half g_wq_h  [DIM * HID];
__device__ __half g_wkv_h [DIM * 2 * HID];
__device__ __half g_wo_h  [HID * DIM];

// ---------------- fp32 -> fp16 convert ----------------
__global__ void cvt_f2h(const float* __restrict__ s, __half* __restrict__ d, int n) {
    int i = blockIdx.x * 256 + threadIdx.x;
    if (i < n) d[i] = __float2half(s[i]);
}

// ---------------- block reduction (deadlock-free) ----------------
template<int NT>
__device__ __forceinline__ float block_sum(float v) {
    __shared__ float sh[32];
    #pragma unroll
    for (int o = 16; o; o >>= 1) v += __shfl_xor_sync(0xffffffffu, v, o);
    if ((threadIdx.x & 31) == 0) sh[threadIdx.x >> 5] = v;
    __syncthreads();
    if (threadIdx.x < 32) {
        float x = (threadIdx.x < NT / 32) ? sh[threadIdx.x] : 0.f;
        #pragma unroll
        for (int o = 16; o; o >>= 1) x += __shfl_xor_sync(0xffffffffu, x, o);
        if (threadIdx.x == 0) sh[0] = x;
    }
    __syncthreads();
    v = sh[0];
    __syncthreads();
    return v;
}

// ---------------- LayerNorm -> fp16 output ----------------
__global__ __launch_bounds__(128) void ln_kernel(
    const float* __restrict__ x, const float* __restrict__ gamma,
    const float* __restrict__ beta, __half* __restrict__ y)
{
    const float* xr = x + (size_t)blockIdx.x * DIM;
    __half* yr = y + (size_t)blockIdx.x * DIM;
    float v[4];
    float s = 0.f;
    #pragma unroll
    for (int i = 0; i < 4; i++) { v[i] = xr[threadIdx.x + 128 * i]; s += v[i]; }
    float mu = block_sum<128>(s) * (1.f / DIM);
    float var = 0.f;
    #pragma unroll
    for (int i = 0; i < 4; i++) { float d = v[i] - mu; var += d * d; }
    var = block_sum<128>(var) * (1.f / DIM);
    float r = rsqrtf(var + LNEPS);
    #pragma unroll
    for (int i = 0; i < 4; i++) {
        int c = threadIdx.x + 128 * i;
        yr[c] = __float2half((v[i] - mu) * r * gamma[c] + beta[c]);
    }
}

// ======== wmma GEMM + bias: C[M,N] = A_h[M,K] @ B_h[K,N] + bias ========
template<bool OUT_HALF>
__global__ __launch_bounds__(256) void gemm_wmma(
    const __half* __restrict__ A, const __half* __restrict__ B,
    const float* __restrict__ bias, void* __restrict__ Cv,
    int M, int N, int K)
{
    __shared__ __half As[128 * 40];
    __shared__ __half Bs[32 * 136];
    __shared__ float  stage[8][16 * 20];
    const int t = threadIdx.x, w = t >> 5, lane = t & 31;
    const int wr = w >> 1, wc = w & 1;
    const int i0 = blockIdx.y * 128, j0 = blockIdx.x * 128;
    wmma::fragment<wmma::accumulator, 16, 16, 16, float> acc[2][4];
    #pragma unroll
    for (int m = 0; m < 2; m++)
        #pragma unroll
        for (int n = 0; n < 4; n++) wmma::fill_fragment(acc[m][n], 0.f);

    for (int kt = 0; kt < K; kt += 32) {
        #pragma unroll
        for (int c = t; c < 512; c += 256) {
            int r = c >> 2, cc = (c & 3) << 3;
            *(uint4*)&As[r * 40 + cc] = *(const uint4*)&A[(size_t)(i0 + r) * K + kt + cc];
        }
        #pragma unroll
        for (int c = t; c < 512; c += 256) {
            int r = c >> 4, cc = (c & 15) << 3;
            *(uint4*)&Bs[r * 136 + cc] = *(const uint4*)&B[(size_t)(kt + r) * N + j0 + cc];
        }
        __syncthreads();
        #pragma unroll
        for (int kk = 0; kk < 2; kk++) {
            wmma::fragment<wmma::matrix_a, 16, 16, 16, __half, wmma::row_major> af[2];
            wmma::fragment<wmma::matrix_b, 16, 16, 16, __half, wmma::row_major> bf[4];
            #pragma unroll
            for (int m = 0; m < 2; m++)
                wmma::load_matrix_sync(af[m], &As[(wr * 32 + m * 16) * 40 + kk * 16], 40);
            #pragma unroll
            for (int n = 0; n < 4; n++)
                wmma::load_matrix_sync(bf[n], &Bs[(kk * 16) * 136 + wc * 64 + n * 16], 136);
            #pragma unroll
            for (int m = 0; m < 2; m++)
                #pragma unroll
                for (int n = 0; n < 4; n++)
                    wmma::mma_sync(acc[m][n], af[m], bf[n], acc[m][n]);
        }
        __syncthreads();
    }
    #pragma unroll
    for (int m = 0; m < 2; m++)
        #pragma unroll
        for (int n = 0; n < 4; n++) {
            wmma::store_matrix_sync(stage[w], acc[m][n], 20, wmma::mem_row_major);
            __syncwarp();
            int row = lane >> 1, c0 = (lane & 1) << 3;
            int gi = i0 + wr * 32 + m * 16 + row;
            int gj = j0 + wc * 64 + n * 16 + c0;
            #pragma unroll
            for (int c = 0; c < 8; c++) {
                float vv = stage[w][row * 20 + c0 + c] + bias[gj + c];
                if (OUT_HALF) ((__half*)Cv)[(size_t)gi * N + gj + c] = __float2half(vv);
                else          ((float*)Cv)[(size_t)gi * N + gj + c] = vv;
            }
            __syncwarp();
        }
}

// ======== p = exp(scale * q kᵀ) per (b,h), fp16 out (max-free softmax) ========
__global__ __launch_bounds__(256) void sim_wmma(
    const __half* __restrict__ q, const __half* __restrict__ kv,
    __half* __restrict__ p)
{
    __shared__ __half As[128 * 72];
    __shared__ __half Bs[128 * 72];
    __shared__ float  stage[8][16 * 20];
    const int bh = blockIdx.z, b = bh / NH, h = bh % NH;
    const __half* A  = q  + (size_t)b * NSINK * HID + h * HD;
    const __half* Bk = kv + (size_t)b * NSRC * (2 * HID) + h * HD;
    __half* C = p + (size_t)bh * NSINK * NSRC;
    const int t = threadIdx.x, w = t >> 5, lane = t & 31;
    const int wr = w >> 1, wc = w & 1;
    const int i0 = blockIdx.y * 128, j0 = blockIdx.x * 128;

    #pragma unroll
    for (int c = t; c < 1024; c += 256) {
        int r = c >> 3, cc = (c & 7) << 3;
        *(uint4*)&As[r * 72 + cc] = *(const uint4*)&A[(size_t)(i0 + r) * HID + cc];
    }
    #pragma unroll
    for (int c = t; c < 1024; c += 256) {
        int r = c >> 3, cc = (c & 7) << 3;
        *(uint4*)&Bs[r * 72 + cc] = *(const uint4*)&Bk[(size_t)(j0 + r) * (2 * HID) + cc];
    }
    __syncthreads();

    wmma::fragment<wmma::accumulator, 16, 16, 16, float> acc[2][4];
    #pragma unroll
    for (int m = 0; m < 2; m++)
        #pragma unroll
        for (int n = 0; n < 4; n++) wmma::fill_fragment(acc[m][n], 0.f);
    #pragma unroll
    for (int kk = 0; kk < 4; kk++) {
        wmma::fragment<wmma::matrix_a, 16, 16, 16, __half, wmma::row_major> af[2];
        wmma::fragment<wmma::matrix_b, 16, 16, 16, __half, wmma::col_major> bf[4];
        #pragma unroll
        for (int m = 0; m < 2; m++)
            wmma::load_matrix_sync(af[m], &As[(wr * 32 + m * 16) * 72 + kk * 16], 72);
        #pragma unroll
        for (int n = 0; n < 4; n++)
            wmma::load_matrix_sync(bf[n], &Bs[(wc * 64 + n * 16) * 72 + kk * 16], 72);
        #pragma unroll
        for (int m = 0; m < 2; m++)
            #pragma unroll
            for (int n = 0; n < 4; n++)
                wmma::mma_sync(acc[m][n], af[m], bf[n], acc[m][n]);
    }
    #pragma unroll
    for (int m = 0; m < 2; m++)
        #pragma unroll
        for (int n = 0; n < 4; n++) {
            wmma::store_matrix_sync(stage[w], acc[m][n], 20, wmma::mem_row_major);
            __syncwarp();
            int row = lane >> 1, c0 = (lane & 1) << 3;
            int gi = i0 + wr * 32 + m * 16 + row;
            int gj = j0 + wc * 64 + n * 16 + c0;
            #pragma unroll
            for (int c = 0; c < 8; c++)
                C[(size_t)gi * NSRC + gj + c] =
                    __float2half(__expf(stage[w][row * 20 + c0 + c] * 0.125f));
            __syncwarp();
        }
}

// ======== colsum: z_j = sum_i p_ij ; store 1/z (pure bandwidth) ========
__global__ __launch_bounds__(256) void colsum_h(
    const __half* __restrict__ p, float* __restrict__ colz)
{
    const int bh = blockIdx.y;
    const int j = blockIdx.x * 512 + threadIdx.x * 2;
    const __half* P = p + (size_t)bh * NSINK * NSRC + j;
    float2 z0 = {0.f, 0.f}, z1 = {0.f, 0.f}, z2 = {0.f, 0.f}, z3 = {0.f, 0.f};
    #pragma unroll 1
    for (int i = 0; i < NSINK; i += 4) {        // 4 independent partial sums
        float2 a = __half22float2(*(const __half2*)&P[(size_t)(i + 0) * NSRC]);
        float2 b = __half22float2(*(const __half2*)&P[(size_t)(i + 1) * NSRC]);
        float2 c = __half22float2(*(const __half2*)&P[(size_t)(i + 2) * NSRC]);
        float2 d = __half22float2(*(const __half2*)&P[(size_t)(i + 3) * NSRC]);
        z0.x += a.x; z0.y += a.y;
        z1.x += b.x; z1.y += b.y;
        z2.x += c.x; z2.y += c.y;
        z3.x += d.x; z3.y += d.y;
    }
    colz[bh * NSRC + j]     = 1.f / (z0.x + z1.x + z2.x + z3.x);
    colz[bh * NSRC + j + 1] = 1.f / (z0.y + z1.y + z2.y + z3.y);
}

// ======== out = (attn @ V_ext) / rowsum; attn = p*invz + eps (no exp) ========
// 64-row i-tile, 4 warps => 256 blocks. Ones column at n=64 gives row sums.
__global__ __launch_bounds__(128) void av_wmma(
    const __half* __restrict__ p, const __half* __restrict__ kv,
    const float* __restrict__ colz, __half* __restrict__ o)
{
    __shared__ __half As[64 * 72];     // attn [i][j64] ld 72
    __shared__ __half Bs[64 * 88];     // V_ext [j][88] ld 88
    __shared__ float  stage[4][16 * 20];
    __shared__ float  rs[4][16];
    const int bh = blockIdx.z, b = bh / NH, h = bh % NH;
    const __half* A = p + (size_t)bh * NSINK * NSRC;
    const __half* V = kv + (size_t)b * NSRC * (2 * HID) + HID + h * HD;
    const float* cz = colz + bh * NSRC;
    const int t = threadIdx.x, w = t >> 5, lane = t & 31;
    const int i0 = blockIdx.y * 64;

    wmma::fragment<wmma::accumulator, 16, 16, 16, float> acc[5];
    #pragma unroll
    for (int n = 0; n < 5; n++) wmma::fill_fragment(acc[n], 0.f);

    for (int kt = 0; kt < NSRC; kt += 64) {
        // attn tile 64x64: 2048 half2, 16 per thread — fma only
        #pragma unroll
        for (int e = t; e < 2048; e += 128) {
            int r = e >> 5, c2 = e & 31;
            int j = kt + c2 * 2;
            float2 pf = __half22float2(*(const __half2*)&A[(size_t)(i0 + r) * NSRC + j]);
            float2 zf = *(const float2*)&cz[j];
            *(__half2*)&As[r * 72 + c2 * 2] =
                __floats2half2_rn(pf.x * zf.x + ATTEPS, pf.y * zf.y + ATTEPS);
        }
        // V tile 64x64
        #pragma unroll
        for (int c = t; c < 512; c += 128) {
            int r = c >> 3, cc = (c & 7) << 3;
            *(uint4*)&Bs[r * 88 + cc] = *(const uint4*)&V[(size_t)(kt + r) * (2 * HID) + cc];
        }
        // extension cols 64..87: ones column + zero pad
        #pragma unroll
        for (int e = t; e < 64 * 24; e += 128) {
            int r = e / 24, cc = 64 + e % 24;
            Bs[r * 88 + cc] = __float2half(cc == 64 ? 1.f : 0.f);
        }
        __syncthreads();
        #pragma unroll
        for (int kk = 0; kk < 4; kk++) {
            wmma::fragment<wmma::matrix_a, 16, 16, 16, __half, wmma::row_major> af;
            wmma::load_matrix_sync(af, &As[(w * 16) * 72 + kk * 16], 72);
            #pragma unroll
            for (int n = 0; n < 5; n++) {
                wmma::fragment<wmma::matrix_b, 16, 16, 16, __half, wmma::row_major> bf;
                wmma::load_matrix_sync(bf, &Bs[(kk * 16) * 88 + n * 16], 88);
                wmma::mma_sync(acc[n], af, bf, acc[n]);
            }
        }
        __syncthreads();
    }
    wmma::store_matrix_sync(stage[w], acc[4], 20, wmma::mem_row_major);
    __syncwarp();
    if (lane < 16) rs[w][lane] = 1.f / stage[w][lane * 20 + 0];
    __syncwarp();
    #pragma unroll
    for (int n = 0; n < 4; n++) {
        wmma::store_matrix_sync(stage[w], acc[n], 20, wmma::mem_row_major);
        __syncwarp();
        int row = lane >> 1, c0 = (lane & 1) << 3;
        int gi = i0 + w * 16 + row;
        #pragma unroll
        for (int c = 0; c < 8; c++)
            o[(size_t)(b * NSINK + gi) * HID + h * HD + n * 16 + c0 + c] =
                __float2half(stage[w][row * 20 + c0 + c] * rs[w][row]);
        __syncwarp();
    }
}

// ---------------- launch ----------------
extern "C" void kernel_launch(void* const* d_in, const int* in_sizes, int n_in,
                              void* d_out, int out_size)
{
    const float* sink    = (const float*)d_in[0];
    const float* source  = (const float*)d_in[1];
    const float* gamma_s = (const float*)d_in[2];
    const float* beta_s  = (const float*)d_in[3];
    const float* gamma_c = (const float*)d_in[4];
    const float* beta_c  = (const float*)d_in[5];
    const float* Wq      = (const float*)d_in[6];
    const float* bq      = (const float*)d_in[7];
    const float* Wkv     = (const float*)d_in[8];
    const float* bkv     = (const float*)d_in[9];
    const float* Wo      = (const float*)d_in[10];
    const float* bo      = (const float*)d_in[11];
    float* out = (float*)d_out;

    __half *snorm_h, *cnorm_h, *q_h, *kv_h, *p_h, *o_h, *wq_h, *wkv_h, *wo_h;
    float *colz;
    cudaGetSymbolAddress((void**)&snorm_h, g_snorm_h);
    cudaGetSymbolAddress((void**)&cnorm_h, g_cnorm_h);
    cudaGetSymbolAddress((void**)&q_h,     g_q_h);
    cudaGetSymbolAddress((void**)&kv_h,    g_kv_h);
    cudaGetSymbolAddress((void**)&p_h,     g_p_h);
    cudaGetSymbolAddress((void**)&colz,    g_colz);
    cudaGetSymbolAddress((void**)&o_h,     g_o_h);
    cudaGetSymbolAddress((void**)&wq_h,    g_wq_h);
    cudaGetSymbolAddress((void**)&wkv_h,   g_wkv_h);
    cudaGetSymbolAddress((void**)&wo_h,    g_wo_h);

    // 0. weight conversion
    cvt_f2h<<<(DIM * HID + 255) / 256, 256>>>(Wq, wq_h, DIM * HID);
    cvt_f2h<<<(DIM * 2 * HID + 255) / 256, 256>>>(Wkv, wkv_h, DIM * 2 * HID);
    cvt_f2h<<<(HID * DIM + 255) / 256, 256>>>(Wo, wo_h, HID * DIM);

    // 1. pre-norms (fp16 out)
    ln_kernel<<<BATCH * NSINK, 128>>>(sink, gamma_s, beta_s, snorm_h);
    ln_kernel<<<BATCH * NSRC, 128>>>(source, gamma_c, beta_c, cnorm_h);

    // 2. projections (tensor cores)
    gemm_wmma<true><<<dim3(HID / 128, BATCH * NSINK / 128), 256>>>(
        snorm_h, wq_h, bq, q_h, BATCH * NSINK, HID, DIM);
    gemm_wmma<true><<<dim3(2 * HID / 128, BATCH * NSRC / 128), 256>>>(
        cnorm_h, wkv_h, bkv, kv_h, BATCH * NSRC, 2 * HID, DIM);

    // 3. p = exp(scale * q kᵀ)  (max-free; |sim| small by construction)
    sim_wmma<<<dim3(NSRC / 128, NSINK / 128, BATCH * NH), 256>>>(q_h, kv_h, p_h);

    // 4. column sums -> 1/z
    colsum_h<<<dim3(NSRC / 512, BATCH * NH), 256>>>(p_h, colz);

    // 5. AV with fused renorm (ones-column trick), 256 blocks
    av_wmma<<<dim3(1, NSINK / 64, BATCH * NH), 128>>>(p_h, kv_h, colz, o_h);

    // 6. output projection (fp32 out)
    gemm_wmma<false><<<dim3(DIM / 128, BATCH * NSINK / 128), 256>>>(
        o_h, wo_h, bo, out, BATCH * NSINK, DIM, DIM);
}